// round 1
// baseline (speedup 1.0000x reference)
#include <cuda_runtime.h>
#include <cstdint>

#define B      64
#define T      256
#define N_IN   128
#define N_HID  2048
#define NB     128            // persistent CTAs (1 per SM, 128*16 = 2048 cols)
#define TILE_J 16             // columns of A per CTA
#define NTHREADS 256
#define OUT_HALF (B*T*N_HID)  // 33554432 floats: mems then spikes
#define SBW (N_HID/32)        // 64 words of spike bits per batch

// ---------------- scratch (static device memory; no allocations) ----------------
__device__ float        g_U[B*T*N_HID];          // U = x@W_in + bias, precomputed
__device__ unsigned int g_sbits[2][B*SBW];       // double-buffered packed spikes
__device__ unsigned int g_arrive;                // grid barrier arrival counter
__device__ volatile unsigned int g_epoch;        // grid barrier release epoch

// ---------------- init: reset barrier + zero initial spikes ----------------
__global__ void init_kernel() {
    int t = threadIdx.x;
    if (t == 0) { g_arrive = 0u; g_epoch = 0u; }
    for (int i = t; i < B*SBW; i += blockDim.x) g_sbits[0][i] = 0u;
}

// ---------------- U = x @ W_in + bias  (M=B*T=16384, K=128, N=2048) ----------------
__global__ void u_kernel(const float* __restrict__ x,
                         const float* __restrict__ W,
                         const float* __restrict__ bias) {
    __shared__ float  xs[16][N_IN];      // 8 KB
    __shared__ float4 Ws[N_IN][16];      // 32 KB (64 cols as float4)
    const int bt0 = blockIdx.x * 16;
    const int j0  = blockIdx.y * 64;
    const int t   = threadIdx.x;

    for (int idx = t; idx < 16*N_IN; idx += NTHREADS)
        xs[idx >> 7][idx & 127] = x[(size_t)(bt0 + (idx >> 7))*N_IN + (idx & 127)];
    for (int idx = t; idx < N_IN*16; idx += NTHREADS) {
        int k = idx >> 4, c4 = idx & 15;
        Ws[k][c4] = *(const float4*)&W[(size_t)k*N_HID + j0 + c4*4];
    }
    __syncthreads();

    const int r = t >> 4, c4 = t & 15;
    float4 acc = *(const float4*)&bias[j0 + c4*4];
    #pragma unroll 8
    for (int k = 0; k < N_IN; k++) {
        float  xv = xs[r][k];
        float4 wv = Ws[k][c4];
        acc.x += xv*wv.x; acc.y += xv*wv.y; acc.z += xv*wv.z; acc.w += xv*wv.w;
    }
    *(float4*)&g_U[(size_t)(bt0 + r)*N_HID + j0 + c4*4] = acc;
}

// ---------------- grid barrier (all NB CTAs co-resident; monotonic epoch) ----------------
__device__ __forceinline__ void grid_barrier(unsigned target) {
    __threadfence();          // flush this thread's global stores to GPU scope
    __syncthreads();
    if (threadIdx.x == 0) {
        unsigned old = atomicAdd(&g_arrive, 1u);
        if ((old & (NB - 1u)) == (NB - 1u)) {
            __threadfence();
            g_epoch = target;                 // release
        } else {
            while (g_epoch < target) { }      // volatile spin (L2)
        }
        __threadfence();
    }
    __syncthreads();
}

// ---------------- persistent step kernel ----------------
// CTA c owns cols [c*16, c*16+16). thread: b = tid>>2 (batch), jg = tid&3 (4 cols).
__global__ void __launch_bounds__(NTHREADS, 1)
step_kernel(const float* __restrict__ A,
            const float* __restrict__ mem0,
            float* __restrict__ out) {
    extern __shared__ unsigned char smem_raw[];
    float*    As = (float*)smem_raw;                                  // [2048][16] fp32
    unsigned* sb = (unsigned*)(smem_raw + (size_t)N_HID*TILE_J*4);    // [B*SBW] = 4096 words

    const int c   = blockIdx.x;
    const int tid = threadIdx.x;
    const int b   = tid >> 2;
    const int jg  = tid & 3;
    const int j0  = c*TILE_J + jg*4;

    // load A column tile into SMEM (once)
    for (int idx = tid; idx < N_HID*TILE_J; idx += NTHREADS) {
        int i = idx >> 4, jj = idx & 15;
        As[idx] = A[(size_t)i*N_HID + c*TILE_J + jj];
    }

    float4 mem = *(const float4*)&mem0[(size_t)b*N_HID + j0];
    float4 spk = make_float4(0.f, 0.f, 0.f, 0.f);
    __syncthreads();

    const ulonglong2* As2 = (const ulonglong2*)As;   // row = 4 x ulonglong2 (16 floats)

    for (int st = 0; st < T; st++) {
        // --- pull this step's spike bits (written by all CTAs last step) into SMEM
        const unsigned* gb = g_sbits[st & 1];
        for (int idx = tid; idx < B*SBW; idx += NTHREADS)
            sb[idx] = __ldcg(&gb[idx]);
        __syncthreads();

        // --- r[b][j0..j0+3] = sum over i with spike(b,i)=1 of A[i][j]  (exact fp32)
        unsigned long long acc01 = 0ull, acc23 = 0ull;
        const unsigned* wrow = sb + b*SBW;
        for (int iw = 0; iw < SBW; iw++) {
            unsigned w = wrow[iw];
            const ulonglong2* p = As2 + (size_t)(iw*32)*4 + jg;
            #pragma unroll
            for (int bit = 0; bit < 32; bit++) {
                ulonglong2 a = p[(size_t)bit*4];
                asm("{\n\t.reg .pred p;\n\t"
                    "setp.ne.b32 p, %4, 0;\n\t"
                    "@p add.rn.f32x2 %0, %0, %2;\n\t"
                    "@p add.rn.f32x2 %1, %1, %3;\n\t}"
                    : "+l"(acc01), "+l"(acc23)
                    : "l"(a.x), "l"(a.y), "r"(w & (1u << bit)));
            }
        }
        float r0, r1, r2, r3;
        asm("mov.b64 {%0,%1}, %2;" : "=f"(r0), "=f"(r1) : "l"(acc01));
        asm("mov.b64 {%0,%1}, %2;" : "=f"(r2), "=f"(r3) : "l"(acc23));

        // --- elementwise update (ordering matches reference op-for-op)
        const size_t base = (size_t)(b*T + st)*N_HID + j0;
        const float4 Uv = *(const float4*)&g_U[base];
        float4 y;
        y.x = tanhf(0.5f*r0 + 0.5f*Uv.x);
        y.y = tanhf(0.5f*r1 + 0.5f*Uv.y);
        y.z = tanhf(0.5f*r2 + 0.5f*Uv.z);
        y.w = tanhf(0.5f*r3 + 0.5f*Uv.w);

        mem.x = mem.x*0.5f - 0.5f*(1.0f - spk.x) + y.x;
        mem.y = mem.y*0.5f - 0.5f*(1.0f - spk.y) + y.y;
        mem.z = mem.z*0.5f - 0.5f*(1.0f - spk.z) + y.z;
        mem.w = mem.w*0.5f - 0.5f*(1.0f - spk.w) + y.w;

        spk.x = (mem.x > 0.5f) ? 1.0f : 0.0f;
        spk.y = (mem.y > 0.5f) ? 1.0f : 0.0f;
        spk.z = (mem.z > 0.5f) ? 1.0f : 0.0f;
        spk.w = (mem.w > 0.5f) ? 1.0f : 0.0f;

        *(float4*)&out[base]            = mem;
        *(float4*)&out[OUT_HALF + base] = spk;

        // --- pack this CTA's 16 spike bits per batch, publish to global
        unsigned mynib = (spk.x != 0.f ? 1u : 0u) | (spk.y != 0.f ? 2u : 0u)
                       | (spk.z != 0.f ? 4u : 0u) | (spk.w != 0.f ? 8u : 0u);
        __syncthreads();                      // GEMM reads of sb complete
        if (tid < B) sb[tid] = 0u;            // reuse sb[0..63] as staging
        __syncthreads();
        atomicOr(&sb[b], mynib << (jg*4));
        __syncthreads();
        if (tid < B) {
            unsigned short v = (unsigned short)sb[tid];
            ((unsigned short*)g_sbits[(st + 1) & 1])[(size_t)tid*(N_HID/16) + c] = v;
        }
        grid_barrier((unsigned)(st + 1));
    }
}

// ---------------- launch ----------------
extern "C" void kernel_launch(void* const* d_in, const int* in_sizes, int n_in,
                              void* d_out, int out_size) {
    const float* x    = (const float*)d_in[0];
    const float* W_in = (const float*)d_in[1];
    const float* A    = (const float*)d_in[2];
    const float* bias = (const float*)d_in[3];
    const float* mem0 = (const float*)d_in[4];
    float* out = (float*)d_out;

    const int smem_bytes = N_HID*TILE_J*4 + B*SBW*4;   // 131072 + 16384 = 147456

    cudaFuncSetAttribute(step_kernel, cudaFuncAttributeMaxDynamicSharedMemorySize,
                         smem_bytes);

    init_kernel<<<1, 256>>>();
    u_kernel<<<dim3((B*T)/16, N_HID/64), NTHREADS>>>(x, W_in, bias);
    step_kernel<<<NB, NTHREADS, smem_bytes>>>(A, mem0, out);
}

// round 2
// speedup vs baseline: 1.3787x; 1.3787x over previous
#include <cuda_runtime.h>
#include <cstdint>

#define B      64
#define T      256
#define N_IN   128
#define N_HID  2048
#define NB     128            // persistent CTAs (1 per SM, 128*16 = 2048 cols)
#define TILE_J 16             // columns of A per CTA
#define NTH    512            // step kernel threads
#define OUT_HALF (B*T*N_HID)  // 33554432 floats: mems then spikes
#define SBW (N_HID/32)        // 64 words of spike bits per batch

// SMEM layout for step kernel
#define SM_AS_BYTES   (N_HID*TILE_J*4)         // 131072
#define SM_SB_OFF     SM_AS_BYTES              // spike bits: 16384 B
#define SM_SB_BYTES   (B*SBW*4)
#define SM_RED_OFF    (SM_SB_OFF + SM_SB_BYTES)   // 147456
#define SLICE_STRIDE  4112                     // 64*16*4 + 16 pad (16B aligned, bank-skewed)
#define SM_RED_BYTES  (16*SLICE_STRIDE)        // 65792
#define SM_TOTAL      (SM_RED_OFF + SM_RED_BYTES) // 213248

// ---------------- scratch (static device memory; no allocations) ----------------
__device__ float        g_U[B*T*N_HID];          // U = x@W_in + bias, precomputed
__device__ unsigned int g_sbits[2][B*SBW];       // double-buffered packed spikes
__device__ unsigned int g_arrive;                // grid barrier arrival counter
__device__ volatile unsigned int g_epoch;        // grid barrier release epoch

// ---------------- U = x @ W_in + bias; block(0,0) also resets barrier/spikes ----------------
__global__ void u_kernel(const float* __restrict__ x,
                         const float* __restrict__ W,
                         const float* __restrict__ bias) {
    __shared__ float  xs[16][N_IN];      // 8 KB
    __shared__ float4 Ws[N_IN][16];      // 32 KB
    const int bt0 = blockIdx.x * 16;
    const int j0  = blockIdx.y * 64;
    const int t   = threadIdx.x;

    if (blockIdx.x == 0 && blockIdx.y == 0) {   // per-launch init (graph-replay safe)
        if (t == 0) { g_arrive = 0u; g_epoch = 0u; }
        for (int i = t; i < B*SBW; i += 256) g_sbits[0][i] = 0u;
    }

    for (int idx = t; idx < 16*N_IN; idx += 256)
        xs[idx >> 7][idx & 127] = x[(size_t)(bt0 + (idx >> 7))*N_IN + (idx & 127)];
    for (int idx = t; idx < N_IN*16; idx += 256) {
        int k = idx >> 4, c4 = idx & 15;
        Ws[k][c4] = *(const float4*)&W[(size_t)k*N_HID + j0 + c4*4];
    }
    __syncthreads();

    const int r = t >> 4, c4 = t & 15;
    float4 acc = *(const float4*)&bias[j0 + c4*4];
    #pragma unroll 8
    for (int k = 0; k < N_IN; k++) {
        float  xv = xs[r][k];
        float4 wv = Ws[k][c4];
        acc.x += xv*wv.x; acc.y += xv*wv.y; acc.z += xv*wv.z; acc.w += xv*wv.w;
    }
    *(float4*)&g_U[(size_t)(bt0 + r)*N_HID + j0 + c4*4] = acc;
}

// ---------------- grid barrier (all NB CTAs co-resident; monotonic epoch) ----------------
__device__ __forceinline__ void grid_barrier(unsigned target) {
    __threadfence();
    __syncthreads();
    if (threadIdx.x == 0) {
        unsigned old = atomicAdd(&g_arrive, 1u);
        if ((old & (NB - 1u)) == (NB - 1u)) {
            __threadfence();
            g_epoch = target;                 // release
        } else {
            while (g_epoch < target) { }      // volatile spin (L2)
        }
        __threadfence();
    }
    __syncthreads();
}

// ---------------- persistent step kernel ----------------
// CTA c owns cols [c*16, c*16+16).
// GEMM phase thread map: jg = tid&3 (col quad), kp = (tid>>2)&7 (row interleave),
//                        bg = (tid>>5)&7 (batch group of 8), kh = tid>>8 (K half).
// Lane reads As[kh*1024 + 8t + kp][jg*4..+3]: a warp's 32 lanes cover one
// contiguous 512B block -> 4 clean smem wavefronts, every byte useful, and each
// 16B A-load feeds 8 batches (16 predicated f32x2 adds).
__global__ void __launch_bounds__(NTH, 1)
step_kernel(const float* __restrict__ A,
            const float* __restrict__ mem0,
            float* __restrict__ out) {
    extern __shared__ unsigned char smem_raw[];
    float*    As  = (float*)smem_raw;
    unsigned* sb  = (unsigned*)(smem_raw + SM_SB_OFF);
    unsigned char* red = smem_raw + SM_RED_OFF;

    const int c   = blockIdx.x;
    const int tid = threadIdx.x;
    const int jg  = tid & 3;
    const int kp  = (tid >> 2) & 7;
    const int bg  = (tid >> 5) & 7;
    const int kh  = tid >> 8;

    // load A column tile into SMEM (once): As[row][16 cols]
    for (int idx = tid; idx < N_HID*TILE_J; idx += NTH) {
        int i = idx >> 4, jj = idx & 15;
        As[idx] = A[(size_t)i*N_HID + c*TILE_J + jj];
    }

    // epilogue-thread persistent state (tid < 256): b = tid>>2, cols j0..j0+3
    float4 mem = make_float4(0.f,0.f,0.f,0.f);
    float4 spk = make_float4(0.f,0.f,0.f,0.f);
    const int b_e  = tid >> 2;               // valid when tid < 256
    const int j0_e = c*TILE_J + jg*4;
    if (tid < 256)
        mem = *(const float4*)&mem0[(size_t)b_e*N_HID + j0_e];
    __syncthreads();

    // per-thread GEMM constants
    const unsigned m0 = 1u << kp;
    const unsigned mqa[4] = { m0, m0 << 8, m0 << 16, m0 << 24 };
    const unsigned char* Ab0 = (const unsigned char*)As + (kh*1024 + kp)*64 + jg*16;
    const unsigned* wbase = sb + (bg*8)*SBW + kh*32;
    unsigned char* rp = red + (kh*8 + kp)*SLICE_STRIDE + (bg*8)*64 + jg*16;

    for (int st = 0; st < T; st++) {
        // --- pull this step's spike bits into SMEM
        const unsigned* gb = g_sbits[st & 1];
        for (int idx = tid; idx < B*SBW; idx += NTH)
            sb[idx] = __ldcg(&gb[idx]);
        __syncthreads();

        // --- partial r over this thread's row slice (rows = kh*1024 + 8t + kp)
        unsigned long long a0=0,a1=0,a2=0,a3=0,a4=0,a5=0,a6=0,a7=0,
                           a8=0,a9=0,a10=0,a11=0,a12=0,a13=0,a14=0,a15=0;
        const unsigned char* pA = Ab0;
        #pragma unroll 1
        for (int q = 0; q < 32; q++) {
            const unsigned w0 = wbase[0*SBW + q], w1 = wbase[1*SBW + q];
            const unsigned w2 = wbase[2*SBW + q], w3 = wbase[3*SBW + q];
            const unsigned w4 = wbase[4*SBW + q], w5 = wbase[5*SBW + q];
            const unsigned w6 = wbase[6*SBW + q], w7 = wbase[7*SBW + q];
            #pragma unroll
            for (int u = 0; u < 4; u++) {
                const ulonglong2 av = *(const ulonglong2*)(pA + u*512);
                const unsigned msk = mqa[u];
                asm("{\n\t"
                    ".reg .pred pf, p;\n\t"
                    ".reg .b32 tt;\n\t"
                    "setp.ne.u32 pf, 0, 0;\n\t"
                    "lop3.or.b32 tt|p, %18, %26, 0, 0xC0, pf;\n\t"
                    "@p add.rn.f32x2 %0, %0, %16;\n\t"
                    "@p add.rn.f32x2 %1, %1, %17;\n\t"
                    "lop3.or.b32 tt|p, %19, %26, 0, 0xC0, pf;\n\t"
                    "@p add.rn.f32x2 %2, %2, %16;\n\t"
                    "@p add.rn.f32x2 %3, %3, %17;\n\t"
                    "lop3.or.b32 tt|p, %20, %26, 0, 0xC0, pf;\n\t"
                    "@p add.rn.f32x2 %4, %4, %16;\n\t"
                    "@p add.rn.f32x2 %5, %5, %17;\n\t"
                    "lop3.or.b32 tt|p, %21, %26, 0, 0xC0, pf;\n\t"
                    "@p add.rn.f32x2 %6, %6, %16;\n\t"
                    "@p add.rn.f32x2 %7, %7, %17;\n\t"
                    "lop3.or.b32 tt|p, %22, %26, 0, 0xC0, pf;\n\t"
                    "@p add.rn.f32x2 %8, %8, %16;\n\t"
                    "@p add.rn.f32x2 %9, %9, %17;\n\t"
                    "lop3.or.b32 tt|p, %23, %26, 0, 0xC0, pf;\n\t"
                    "@p add.rn.f32x2 %10, %10, %16;\n\t"
                    "@p add.rn.f32x2 %11, %11, %17;\n\t"
                    "lop3.or.b32 tt|p, %24, %26, 0, 0xC0, pf;\n\t"
                    "@p add.rn.f32x2 %12, %12, %16;\n\t"
                    "@p add.rn.f32x2 %13, %13, %17;\n\t"
                    "lop3.or.b32 tt|p, %25, %26, 0, 0xC0, pf;\n\t"
                    "@p add.rn.f32x2 %14, %14, %16;\n\t"
                    "@p add.rn.f32x2 %15, %15, %17;\n\t"
                    "}"
                    : "+l"(a0),"+l"(a1),"+l"(a2),"+l"(a3),
                      "+l"(a4),"+l"(a5),"+l"(a6),"+l"(a7),
                      "+l"(a8),"+l"(a9),"+l"(a10),"+l"(a11),
                      "+l"(a12),"+l"(a13),"+l"(a14),"+l"(a15)
                    : "l"(av.x), "l"(av.y),
                      "r"(w0),"r"(w1),"r"(w2),"r"(w3),
                      "r"(w4),"r"(w5),"r"(w6),"r"(w7),
                      "r"(msk));
            }
            pA += 2048;
        }
        pA = Ab0;

        // --- write partials: red[slice][b][16 cols]
        { ulonglong2 v; 
          v.x=a0;  v.y=a1;  *(ulonglong2*)(rp + 0*64) = v;
          v.x=a2;  v.y=a3;  *(ulonglong2*)(rp + 1*64) = v;
          v.x=a4;  v.y=a5;  *(ulonglong2*)(rp + 2*64) = v;
          v.x=a6;  v.y=a7;  *(ulonglong2*)(rp + 3*64) = v;
          v.x=a8;  v.y=a9;  *(ulonglong2*)(rp + 4*64) = v;
          v.x=a10; v.y=a11; *(ulonglong2*)(rp + 5*64) = v;
          v.x=a12; v.y=a13; *(ulonglong2*)(rp + 6*64) = v;
          v.x=a14; v.y=a15; *(ulonglong2*)(rp + 7*64) = v;
        }
        __syncthreads();

        unsigned mynib = 0u;
        if (tid < 256) {
            // --- reduce 16 partials (fixed slice order)
            const unsigned char* rq = red + tid*16;
            unsigned long long r01 = 0ull, r23 = 0ull;
            #pragma unroll
            for (int s = 0; s < 16; s++) {
                ulonglong2 v = *(const ulonglong2*)(rq + s*SLICE_STRIDE);
                asm("add.rn.f32x2 %0, %0, %1;" : "+l"(r01) : "l"(v.x));
                asm("add.rn.f32x2 %0, %0, %1;" : "+l"(r23) : "l"(v.y));
            }
            float r0, r1, r2, r3;
            asm("mov.b64 {%0,%1}, %2;" : "=f"(r0), "=f"(r1) : "l"(r01));
            asm("mov.b64 {%0,%1}, %2;" : "=f"(r2), "=f"(r3) : "l"(r23));

            // --- elementwise update (ordering matches reference op-for-op)
            const size_t base = (size_t)(b_e*T + st)*N_HID + j0_e;
            const float4 Uv = *(const float4*)&g_U[base];
            float4 y;
            y.x = tanhf(0.5f*r0 + 0.5f*Uv.x);
            y.y = tanhf(0.5f*r1 + 0.5f*Uv.y);
            y.z = tanhf(0.5f*r2 + 0.5f*Uv.z);
            y.w = tanhf(0.5f*r3 + 0.5f*Uv.w);

            mem.x = mem.x*0.5f - 0.5f*(1.0f - spk.x) + y.x;
            mem.y = mem.y*0.5f - 0.5f*(1.0f - spk.y) + y.y;
            mem.z = mem.z*0.5f - 0.5f*(1.0f - spk.z) + y.z;
            mem.w = mem.w*0.5f - 0.5f*(1.0f - spk.w) + y.w;

            spk.x = (mem.x > 0.5f) ? 1.0f : 0.0f;
            spk.y = (mem.y > 0.5f) ? 1.0f : 0.0f;
            spk.z = (mem.z > 0.5f) ? 1.0f : 0.0f;
            spk.w = (mem.w > 0.5f) ? 1.0f : 0.0f;

            *(float4*)&out[base]            = mem;
            *(float4*)&out[OUT_HALF + base] = spk;

            mynib = (spk.x != 0.f ? 1u : 0u) | (spk.y != 0.f ? 2u : 0u)
                  | (spk.z != 0.f ? 4u : 0u) | (spk.w != 0.f ? 8u : 0u);
        }

        // --- pack this CTA's 16 spike bits per batch, publish to global
        __syncthreads();                      // red reads done; sb free for staging
        if (tid < B) sb[tid] = 0u;
        __syncthreads();
        if (tid < 256) atomicOr(&sb[b_e], mynib << (jg*4));
        __syncthreads();
        if (tid < B) {
            unsigned short v = (unsigned short)sb[tid];
            ((unsigned short*)g_sbits[(st + 1) & 1])[(size_t)tid*(N_HID/16) + c] = v;
        }
        grid_barrier((unsigned)(st + 1));
    }
}

// ---------------- launch ----------------
extern "C" void kernel_launch(void* const* d_in, const int* in_sizes, int n_in,
                              void* d_out, int out_size) {
    const float* x    = (const float*)d_in[0];
    const float* W_in = (const float*)d_in[1];
    const float* A    = (const float*)d_in[2];
    const float* bias = (const float*)d_in[3];
    const float* mem0 = (const float*)d_in[4];
    float* out = (float*)d_out;

    cudaFuncSetAttribute(step_kernel, cudaFuncAttributeMaxDynamicSharedMemorySize,
                         SM_TOTAL);

    u_kernel<<<dim3((B*T)/16, N_HID/64), 256>>>(x, W_in, bias);
    step_kernel<<<NB, NTH, SM_TOTAL>>>(A, mem0, out);
}

// round 5
// speedup vs baseline: 4.4929x; 3.2589x over previous
#include <cuda_runtime.h>
#include <cstdint>

#define B      64
#define T      256
#define N_IN   128
#define N_HID  2048
#define NB     128            // persistent CTAs (1 per SM)
#define TILE_J 16             // columns of A per CTA
#define NTH    1024           // step kernel threads
#define OUT_HALF (B*T*N_HID)
#define SBW    64             // spike-bit words per batch

// SMEM layout (step kernel)
#define ROW_STRIDE 20                               // floats per A row (80B: 16B-ALIGNED + bank-skewed)
#define SM_AS_BYTES (N_HID*ROW_STRIDE*4)            // 163840
#define SM_SB_OFF   SM_AS_BYTES
#define SM_SB_BYTES (B*SBW*4)                       // 16384
#define SM_RED_OFF  (SM_SB_OFF + SM_SB_BYTES)
#define SM_RED_BYTES (3*256*16)                     // 12288
#define SM_TOTAL    (SM_RED_OFF + SM_RED_BYTES)     // 192512

// ---------------- scratch (static device memory) ----------------
__device__ float        g_U[B*T*N_HID];
__device__ unsigned int g_sbits[2][B*SBW];
__device__ unsigned int g_arrive;
__device__ volatile unsigned int g_epoch;

// ---------------- U = x @ W_in + bias; block(0,0) also resets barrier/spikes ----------------
__global__ void u_kernel(const float* __restrict__ x,
                         const float* __restrict__ W,
                         const float* __restrict__ bias) {
    __shared__ float  xs[16][N_IN];
    __shared__ float4 Ws[N_IN][16];
    const int bt0 = blockIdx.x * 16;
    const int j0  = blockIdx.y * 64;
    const int t   = threadIdx.x;

    if (blockIdx.x == 0 && blockIdx.y == 0) {
        if (t == 0) { g_arrive = 0u; g_epoch = 0u; }
        for (int i = t; i < B*SBW; i += 256) g_sbits[0][i] = 0u;
    }

    for (int idx = t; idx < 16*N_IN; idx += 256)
        xs[idx >> 7][idx & 127] = x[(size_t)(bt0 + (idx >> 7))*N_IN + (idx & 127)];
    for (int idx = t; idx < N_IN*16; idx += 256) {
        int k = idx >> 4, c4 = idx & 15;
        Ws[k][c4] = *(const float4*)&W[(size_t)k*N_HID + j0 + c4*4];
    }
    __syncthreads();

    const int r = t >> 4, c4 = t & 15;
    float4 acc = *(const float4*)&bias[j0 + c4*4];
    #pragma unroll 8
    for (int k = 0; k < N_IN; k++) {
        float  xv = xs[r][k];
        float4 wv = Ws[k][c4];
        acc.x += xv*wv.x; acc.y += xv*wv.y; acc.z += xv*wv.z; acc.w += xv*wv.w;
    }
    *(float4*)&g_U[(size_t)(bt0 + r)*N_HID + j0 + c4*4] = acc;
}

// ---------------- grid barrier ----------------
__device__ __forceinline__ void grid_barrier(unsigned target) {
    __threadfence();
    __syncthreads();
    if (threadIdx.x == 0) {
        unsigned old = atomicAdd(&g_arrive, 1u);
        if ((old & (NB - 1u)) == (NB - 1u)) {
            __threadfence();
            g_epoch = target;
        } else {
            while (g_epoch < target) { }
        }
        __threadfence();
    }
    __syncthreads();
}

#define ACC2(av) asm("add.rn.f32x2 %0, %0, %2;\n\t" \
                     "add.rn.f32x2 %1, %1, %3;"     \
                     : "+l"(acc01), "+l"(acc23) : "l"((av).x), "l"((av).y))

// ---------------- persistent step kernel ----------------
// CTA c owns cols [c*16, c*16+16).
// Thread map: jg = tid&3 (col quad), b = (tid>>2)&63 (batch), kq = tid>>8 (K quarter).
// Sparse row-gather: for each set spike bit i in this quarter's 16 words,
// add As[i][jg*4..jg*4+3] into the f32x2 accumulators (depth-1 pipelined LDS).
__global__ void __launch_bounds__(NTH, 1)
step_kernel(const float* __restrict__ A,
            const float* __restrict__ mem0,
            float* __restrict__ out) {
    extern __shared__ unsigned char smem_raw[];
    float*         As  = (float*)smem_raw;                   // [2048][20] fp32 (80B rows)
    unsigned*      sb  = (unsigned*)(smem_raw + SM_SB_OFF);  // [64][64] spike bits
    unsigned char* red = smem_raw + SM_RED_OFF;              // 3 quarters x 256 x 16B

    const int c   = blockIdx.x;
    const int tid = threadIdx.x;
    const int jg  = tid & 3;
    const int b   = (tid >> 2) & 63;
    const int kq  = tid >> 8;

    // load A column tile into SMEM (once), padded rows
    for (int idx = tid; idx < N_HID*TILE_J; idx += NTH) {
        int i = idx >> 4, jj = idx & 15;
        As[i*ROW_STRIDE + jj] = A[(size_t)i*N_HID + c*TILE_J + jj];
    }

    // epilogue-thread persistent state (tid < 256)
    float4 mem = make_float4(0.f,0.f,0.f,0.f);
    float4 spk = make_float4(0.f,0.f,0.f,0.f);
    const int j0_e = c*TILE_J + jg*4;
    if (tid < 256)
        mem = *(const float4*)&mem0[(size_t)b*N_HID + j0_e];
    __syncthreads();

    const unsigned char* Ab = (const unsigned char*)As + jg*16;
    const unsigned* wp = sb + b*SBW + kq*16;

    for (int st = 0; st < T; st++) {
        // prefetch this step's U early (consumed in epilogue)
        const size_t base = (size_t)(b*T + st)*N_HID + j0_e;
        float4 Uv = make_float4(0.f,0.f,0.f,0.f);
        if (tid < 256) Uv = *(const float4*)&g_U[base];

        // pull this step's spike bits into SMEM
        const unsigned* gb = g_sbits[st & 1];
        for (int idx = tid; idx < B*SBW; idx += NTH)
            sb[idx] = __ldcg(&gb[idx]);
        __syncthreads();

        // --- sparse row-gather over this thread's quarter (rows kq*512 .. +511)
        unsigned long long acc01 = 0ull, acc23 = 0ull;
        #pragma unroll 1
        for (int wi = 0; wi < 16; wi++) {
            unsigned w = wp[wi];
            const unsigned char* Aw = Ab + (size_t)(kq*512 + wi*32)*(ROW_STRIDE*4);
            if (w) {
                int i = __ffs((int)w) - 1; w &= w - 1u;
                ulonglong2 av = *(const ulonglong2*)(Aw + i*(ROW_STRIDE*4));
                while (w) {
                    int i2 = __ffs((int)w) - 1; w &= w - 1u;
                    ulonglong2 av2 = *(const ulonglong2*)(Aw + i2*(ROW_STRIDE*4));
                    ACC2(av);                  // add previous while next load is in flight
                    av = av2;
                }
                ACC2(av);
            }
        }

        // --- cross-quarter reduction (fixed order: q0+q1+q2+q3)
        if (kq) {
            ulonglong2 v; v.x = acc01; v.y = acc23;
            *(ulonglong2*)(red + (size_t)(kq-1)*4096 + (tid & 255)*16) = v;
        }
        __syncthreads();

        unsigned mynib = 0u;
        if (tid < 256) {
            #pragma unroll
            for (int s = 0; s < 3; s++) {
                ulonglong2 v = *(const ulonglong2*)(red + (size_t)s*4096 + tid*16);
                ACC2(v);
            }
            float r0, r1, r2, r3;
            asm("mov.b64 {%0,%1}, %2;" : "=f"(r0), "=f"(r1) : "l"(acc01));
            asm("mov.b64 {%0,%1}, %2;" : "=f"(r2), "=f"(r3) : "l"(acc23));

            float4 y;
            y.x = tanhf(0.5f*r0 + 0.5f*Uv.x);
            y.y = tanhf(0.5f*r1 + 0.5f*Uv.y);
            y.z = tanhf(0.5f*r2 + 0.5f*Uv.z);
            y.w = tanhf(0.5f*r3 + 0.5f*Uv.w);

            mem.x = mem.x*0.5f - 0.5f*(1.0f - spk.x) + y.x;
            mem.y = mem.y*0.5f - 0.5f*(1.0f - spk.y) + y.y;
            mem.z = mem.z*0.5f - 0.5f*(1.0f - spk.z) + y.z;
            mem.w = mem.w*0.5f - 0.5f*(1.0f - spk.w) + y.w;

            spk.x = (mem.x > 0.5f) ? 1.0f : 0.0f;
            spk.y = (mem.y > 0.5f) ? 1.0f : 0.0f;
            spk.z = (mem.z > 0.5f) ? 1.0f : 0.0f;
            spk.w = (mem.w > 0.5f) ? 1.0f : 0.0f;

            *(float4*)&out[base]            = mem;
            *(float4*)&out[OUT_HALF + base] = spk;

            mynib = (spk.x != 0.f ? 1u : 0u) | (spk.y != 0.f ? 2u : 0u)
                  | (spk.z != 0.f ? 4u : 0u) | (spk.w != 0.f ? 8u : 0u);
        } else if (tid < 320) {
            sb[tid - 256] = 0u;               // stage area for packing (b = tid-256)
        }
        __syncthreads();
        if (tid < 256) atomicOr(&sb[b], mynib << (jg*4));
        __syncthreads();
        if (tid >= 256 && tid < 320) {
            unsigned short v = (unsigned short)sb[tid - 256];
            ((unsigned short*)g_sbits[(st + 1) & 1])[(size_t)(tid - 256)*(N_HID/16) + c] = v;
        }
        grid_barrier((unsigned)(st + 1));
    }
}

// ---------------- launch ----------------
extern "C" void kernel_launch(void* const* d_in, const int* in_sizes, int n_in,
                              void* d_out, int out_size) {
    const float* x    = (const float*)d_in[0];
    const float* W_in = (const float*)d_in[1];
    const float* A    = (const float*)d_in[2];
    const float* bias = (const float*)d_in[3];
    const float* mem0 = (const float*)d_in[4];
    float* out = (float*)d_out;

    cudaFuncSetAttribute(step_kernel, cudaFuncAttributeMaxDynamicSharedMemorySize,
                         SM_TOTAL);

    u_kernel<<<dim3((B*T)/16, N_HID/64), 256>>>(x, W_in, bias);
    step_kernel<<<NB, NTH, SM_TOTAL>>>(A, mem0, out);
}

// round 6
// speedup vs baseline: 5.2211x; 1.1621x over previous
#include <cuda_runtime.h>
#include <cstdint>

#define B      64
#define T      256
#define N_IN   128
#define N_HID  2048
#define NB     128            // persistent CTAs (1 per SM)
#define TILE_J 16             // columns of A per CTA
#define NTH    1024
#define OUT_HALF (B*T*N_HID)
#define SBW    64             // spike-bit words per batch

// SMEM layout (step kernel)
#define SM_AS_BYTES (N_HID*TILE_J*4)                 // 131072 (swizzled, 64B rows)
#define SM_SB_OFF   SM_AS_BYTES
#define SM_SB_BYTES (B*SBW*4)                        // 16384
#define SM_RED_OFF  (SM_SB_OFF + SM_SB_BYTES)
#define SM_RED_BYTES (3*256*16)                      // 12288
#define SM_W_OFF    (SM_RED_OFF + SM_RED_BYTES)
#define SM_W_BYTES  (N_IN*TILE_J*4)                  // 8192
#define SM_TOTAL    (SM_W_OFF + SM_W_BYTES)          // 167936

// ---------------- scratch ----------------
__device__ unsigned int g_sbits[2][B*SBW];           // double-buffered packed spikes
__device__ unsigned int g_arrive;
__device__ volatile unsigned int g_epoch;

// ---------------- init: reset barrier + zero initial spikes ----------------
__global__ void init_kernel() {
    int t = threadIdx.x;
    if (t == 0) { g_arrive = 0u; g_epoch = 0u; }
    for (int i = t; i < B*SBW; i += blockDim.x) g_sbits[0][i] = 0u;
}

// ---------------- grid barrier ----------------
__device__ __forceinline__ void grid_barrier(unsigned target) {
    __threadfence();
    __syncthreads();
    if (threadIdx.x == 0) {
        unsigned old = atomicAdd(&g_arrive, 1u);
        if ((old & (NB - 1u)) == (NB - 1u)) {
            __threadfence();
            g_epoch = target;
        } else {
            while (g_epoch < target) { }
        }
        __threadfence();
    }
    __syncthreads();
}

#define ACC2(av) asm("add.rn.f32x2 %0, %0, %2;\n\t" \
                     "add.rn.f32x2 %1, %1, %3;"     \
                     : "+l"(acc01), "+l"(acc23) : "l"((av).x), "l"((av).y))

// ---------------- persistent step kernel ----------------
// CTA c owns cols [c*16, c*16+16).
// Thread map: jg = tid&3 (col quad), b = (tid>>2)&63 (batch), kq = tid>>8 (quarter).
// Per step: acc = U-partial (computed LAST iteration, pre-barrier) + sparse
// row-gather over this quarter's spike bits; reduce quarters; epilogue updates
// mem/spike for (b, 4 cols); spikes packed via quad shuffles and published.
__global__ void __launch_bounds__(NTH, 1)
step_kernel(const float* __restrict__ x,
            const float* __restrict__ W_in,
            const float* __restrict__ A,
            const float* __restrict__ bias,
            const float* __restrict__ mem0,
            float* __restrict__ out) {
    extern __shared__ unsigned char smem_raw[];
    float*         As  = (float*)smem_raw;                   // swizzled [2048][16]
    unsigned*      sb  = (unsigned*)(smem_raw + SM_SB_OFF);  // [64][64] spike bits
    unsigned char* red = smem_raw + SM_RED_OFF;
    float*         Ws  = (float*)(smem_raw + SM_W_OFF);      // [128][16]

    const int c    = blockIdx.x;
    const int tid  = threadIdx.x;
    const int lane = tid & 31;
    const int jg   = tid & 3;
    const int b    = (tid >> 2) & 63;
    const int kq   = tid >> 8;

    // A tile, swizzled: word(r,jj) -> r*16 + ((jj>>2 ^ ((r>>1)&3))<<2) + (jj&3)
    for (int idx = tid; idx < N_HID*TILE_J; idx += NTH) {
        int r = idx >> 4, jj = idx & 15;
        int d = (r << 4) + ((((jj >> 2) ^ ((r >> 1) & 3)) << 2)) + (jj & 3);
        As[d] = A[(size_t)r*N_HID + c*TILE_J + jj];
    }
    // W_in tile (plain [k][16])
    for (int idx = tid; idx < N_IN*TILE_J; idx += NTH) {
        int k = idx >> 4, jj = idx & 15;
        Ws[idx] = W_in[(size_t)k*N_HID + c*TILE_J + jj];
    }

    // epilogue persistent state (tid < 256)
    float4 mem = make_float4(0.f,0.f,0.f,0.f);
    float4 spk = make_float4(0.f,0.f,0.f,0.f);
    float4 biasv = make_float4(0.f,0.f,0.f,0.f);
    const int j0_e = c*TILE_J + jg*4;
    if (tid < 256) {
        mem   = *(const float4*)&mem0[(size_t)b*N_HID + j0_e];
        biasv = *(const float4*)&bias[j0_e];
    }
    __syncthreads();

    const unsigned char* Ab   = (const unsigned char*)As;
    const unsigned char* Wb   = (const unsigned char*)Ws + jg*16;
    const unsigned*      wp   = sb + b*SBW + kq*16;
    const int            srcq = lane & 28;            // quad base lane for shfl

    // ---- U-partial for step 0 (pre-loop) ----
    unsigned long long acc01 = 0ull, acc23 = 0ull;
    {
        const float* xp = x + ((size_t)b*T + 0)*N_IN + kq*32 + jg*8;
        float xf[8];
        *(float4*)&xf[0] = *(const float4*)xp;
        *(float4*)&xf[4] = *(const float4*)(xp + 4);
        #pragma unroll
        for (int kk = 0; kk < 32; kk++) {
            float xv = __shfl_sync(0xffffffffu, xf[kk & 7], srcq | (kk >> 3), 32);
            ulonglong2 wv = *(const ulonglong2*)(Wb + (kq*32 + kk)*64);
            unsigned long long xx;
            asm("mov.b64 %0, {%1,%1};" : "=l"(xx) : "f"(xv));
            asm("fma.rn.f32x2 %0, %2, %3, %0;\n\t"
                "fma.rn.f32x2 %1, %2, %4, %1;"
                : "+l"(acc01), "+l"(acc23) : "l"(xx), "l"(wv.x), "l"(wv.y));
        }
    }

    for (int st = 0; st < T; st++) {
        // ---- stage this step's spike bits (1 x LDG.128.cg + STS.128 per thread)
        ((uint4*)sb)[tid] = __ldcg((const uint4*)g_sbits[st & 1] + tid);
        __syncthreads();

        // ---- sparse row-gather (rows kq*512 .. +511) into acc (already holds U)
        #pragma unroll 1
        for (int wi = 0; wi < 16; wi++) {
            unsigned w = wp[wi];
            const int rb = kq*512 + wi*32;
            if (w) {
                int i = __ffs((int)w) - 1; w &= w - 1u;
                int r = rb + i;
                ulonglong2 av = *(const ulonglong2*)(Ab + (r << 6) + ((jg ^ ((r >> 1) & 3)) << 4));
                while (w) {
                    int i2 = __ffs((int)w) - 1; w &= w - 1u;
                    int r2 = rb + i2;
                    ulonglong2 av2 = *(const ulonglong2*)(Ab + (r2 << 6) + ((jg ^ ((r2 >> 1) & 3)) << 4));
                    ACC2(av);
                    av = av2;
                }
                ACC2(av);
            }
        }

        // ---- cross-quarter reduction (fixed order)
        if (kq) {
            ulonglong2 v; v.x = acc01; v.y = acc23;
            *(ulonglong2*)(red + (size_t)(kq-1)*4096 + (tid & 255)*16) = v;
        }
        __syncthreads();

        if (tid < 256) {
            #pragma unroll
            for (int s = 0; s < 3; s++) {
                ulonglong2 v = *(const ulonglong2*)(red + (size_t)s*4096 + tid*16);
                ACC2(v);
            }
            float r0, r1, r2, r3;
            asm("mov.b64 {%0,%1}, %2;" : "=f"(r0), "=f"(r1) : "l"(acc01));
            asm("mov.b64 {%0,%1}, %2;" : "=f"(r2), "=f"(r3) : "l"(acc23));

            float4 y;
            y.x = tanhf(0.5f*r0 + 0.5f*biasv.x);
            y.y = tanhf(0.5f*r1 + 0.5f*biasv.y);
            y.z = tanhf(0.5f*r2 + 0.5f*biasv.z);
            y.w = tanhf(0.5f*r3 + 0.5f*biasv.w);

            mem.x = mem.x*0.5f - 0.5f*(1.0f - spk.x) + y.x;
            mem.y = mem.y*0.5f - 0.5f*(1.0f - spk.y) + y.y;
            mem.z = mem.z*0.5f - 0.5f*(1.0f - spk.z) + y.z;
            mem.w = mem.w*0.5f - 0.5f*(1.0f - spk.w) + y.w;

            spk.x = (mem.x > 0.5f) ? 1.0f : 0.0f;
            spk.y = (mem.y > 0.5f) ? 1.0f : 0.0f;
            spk.z = (mem.z > 0.5f) ? 1.0f : 0.0f;
            spk.w = (mem.w > 0.5f) ? 1.0f : 0.0f;

            const size_t base = (size_t)(b*T + st)*N_HID + j0_e;
            *(float4*)&out[base]            = mem;
            *(float4*)&out[OUT_HALF + base] = spk;

            // ---- pack 16 spike bits via quad shuffles; lane jg==0 publishes
            unsigned v = ((spk.x != 0.f ? 1u : 0u) | (spk.y != 0.f ? 2u : 0u)
                        | (spk.z != 0.f ? 4u : 0u) | (spk.w != 0.f ? 8u : 0u)) << (jg*4);
            v |= __shfl_xor_sync(0xffffffffu, v, 1, 32);
            v |= __shfl_xor_sync(0xffffffffu, v, 2, 32);
            if (jg == 0)
                ((unsigned short*)g_sbits[(st + 1) & 1])[(size_t)b*(N_HID/16) + c] =
                    (unsigned short)v;
        }

        // ---- U-partial for step st+1 (barrier-slack work)
        acc01 = 0ull; acc23 = 0ull;
        if (st + 1 < T) {
            const float* xp = x + ((size_t)b*T + (st + 1))*N_IN + kq*32 + jg*8;
            float xf[8];
            *(float4*)&xf[0] = *(const float4*)xp;
            *(float4*)&xf[4] = *(const float4*)(xp + 4);
            #pragma unroll
            for (int kk = 0; kk < 32; kk++) {
                float xv = __shfl_sync(0xffffffffu, xf[kk & 7], srcq | (kk >> 3), 32);
                ulonglong2 wv = *(const ulonglong2*)(Wb + (kq*32 + kk)*64);
                unsigned long long xx;
                asm("mov.b64 %0, {%1,%1};" : "=l"(xx) : "f"(xv));
                asm("fma.rn.f32x2 %0, %2, %3, %0;\n\t"
                    "fma.rn.f32x2 %1, %2, %4, %1;"
                    : "+l"(acc01), "+l"(acc23) : "l"(xx), "l"(wv.x), "l"(wv.y));
            }
        }

        grid_barrier((unsigned)(st + 1));
    }
}

// ---------------- launch ----------------
extern "C" void kernel_launch(void* const* d_in, const int* in_sizes, int n_in,
                              void* d_out, int out_size) {
    const float* x    = (const float*)d_in[0];
    const float* W_in = (const float*)d_in[1];
    const float* A    = (const float*)d_in[2];
    const float* bias = (const float*)d_in[3];
    const float* mem0 = (const float*)d_in[4];
    float* out = (float*)d_out;

    cudaFuncSetAttribute(step_kernel, cudaFuncAttributeMaxDynamicSharedMemorySize,
                         SM_TOTAL);

    init_kernel<<<1, 256>>>();
    step_kernel<<<NB, NTH, SM_TOTAL>>>(x, W_in, A, bias, mem0, out);
}

// round 8
// speedup vs baseline: 5.8148x; 1.1137x over previous
#include <cuda_runtime.h>
#include <cstdint>

#define B      64
#define T      256
#define N_IN   128
#define N_HID  2048
#define NB     128            // persistent CTAs (1 per SM)
#define TILE_J 16             // columns of A per CTA
#define NTH    1024
#define OUT_HALF (B*T*N_HID)
#define SBW    64             // spike-bit words per batch

// SMEM layout (step kernel)
#define SM_AS_BYTES (N_HID*TILE_J*4)                 // 131072 (swizzled, 64B rows)
#define SM_SB_OFF   SM_AS_BYTES
#define SM_SB_BYTES (B*SBW*4)                        // 16384
#define SM_RED_OFF  (SM_SB_OFF + SM_SB_BYTES)
#define SM_RED_BYTES (3*256*16)                      // 12288
#define SM_W_OFF    (SM_RED_OFF + SM_RED_BYTES)
#define SM_W_BYTES  (N_IN*TILE_J*4)                  // 8192
#define SM_TOTAL    (SM_W_OFF + SM_W_BYTES)          // 167936

// ---------------- scratch ----------------
__device__ unsigned int g_sbits[2][B*SBW];           // double-buffered packed spikes
__device__ unsigned int g_arrive;
__device__ volatile unsigned int g_epoch;

// ---------------- init: reset barrier + zero initial spikes ----------------
__global__ void init_kernel() {
    int t = threadIdx.x;
    if (t == 0) { g_arrive = 0u; g_epoch = 0u; }
    for (int i = t; i < B*SBW; i += blockDim.x) g_sbits[0][i] = 0u;
}

#define ACC2(av) asm("add.rn.f32x2 %0, %0, %2;\n\t" \
                     "add.rn.f32x2 %1, %1, %3;"     \
                     : "+l"(acc01), "+l"(acc23) : "l"((av).x), "l"((av).y))

// ---------------- persistent step kernel ----------------
// CTA c owns cols [c*16, c*16+16).
// Thread map: jg = tid&3 (col quad), b = (tid>>2)&63 (batch), kq = tid>>8 (quarter).
// Per step: acc = U-partial (computed LAST iteration, in barrier slack) + sparse
// row-gather over this quarter's spike bits; reduce quarters; epilogue updates
// mem/spike for (b, 4 cols); spikes packed via quad shuffles and published.
// Grid barrier = CG-style: bar.sync carries cumulativity; ONLY thread 0 fences
// (vs R6's all-1024-threads __threadfence -> 2048 MEMBAR/CCTL.IVALL per step,
// which was the measured L1=58.5% serialization). U(st+1) computed between
// arrive and the volatile spin — true slack, only thread 0 spins.
__global__ void __launch_bounds__(NTH, 1)
step_kernel(const float* __restrict__ x,
            const float* __restrict__ W_in,
            const float* __restrict__ A,
            const float* __restrict__ bias,
            const float* __restrict__ mem0,
            float* __restrict__ out) {
    extern __shared__ unsigned char smem_raw[];
    float*         As  = (float*)smem_raw;                   // swizzled [2048][16]
    unsigned*      sb  = (unsigned*)(smem_raw + SM_SB_OFF);  // [64][64] spike bits
    unsigned char* red = smem_raw + SM_RED_OFF;
    float*         Ws  = (float*)(smem_raw + SM_W_OFF);      // [128][16]

    const int c    = blockIdx.x;
    const int tid  = threadIdx.x;
    const int lane = tid & 31;
    const int jg   = tid & 3;
    const int b    = (tid >> 2) & 63;
    const int kq   = tid >> 8;

    // A tile, swizzled: word(r,jj) -> r*16 + ((jj>>2 ^ ((r>>1)&3))<<2) + (jj&3)
    for (int idx = tid; idx < N_HID*TILE_J; idx += NTH) {
        int r = idx >> 4, jj = idx & 15;
        int d = (r << 4) + ((((jj >> 2) ^ ((r >> 1) & 3)) << 2)) + (jj & 3);
        As[d] = A[(size_t)r*N_HID + c*TILE_J + jj];
    }
    // W_in tile (plain [k][16])
    for (int idx = tid; idx < N_IN*TILE_J; idx += NTH) {
        int k = idx >> 4, jj = idx & 15;
        Ws[idx] = W_in[(size_t)k*N_HID + c*TILE_J + jj];
    }

    // epilogue persistent state (tid < 256)
    float4 mem = make_float4(0.f,0.f,0.f,0.f);
    float4 spk = make_float4(0.f,0.f,0.f,0.f);
    float4 biasv = make_float4(0.f,0.f,0.f,0.f);
    const int j0_e = c*TILE_J + jg*4;
    if (tid < 256) {
        mem   = *(const float4*)&mem0[(size_t)b*N_HID + j0_e];
        biasv = *(const float4*)&bias[j0_e];
    }
    __syncthreads();

    const unsigned char* Ab   = (const unsigned char*)As;
    const unsigned char* Wb   = (const unsigned char*)Ws + jg*16;
    const unsigned*      wp   = sb + b*SBW + kq*16;
    const int            srcq = lane & 28;            // quad base lane for shfl

    // ---- U-partial for step 0 (pre-loop) ----
    unsigned long long acc01 = 0ull, acc23 = 0ull;
    {
        const float* xp = x + ((size_t)b*T + 0)*N_IN + kq*32 + jg*8;
        float xf[8];
        *(float4*)&xf[0] = *(const float4*)xp;
        *(float4*)&xf[4] = *(const float4*)(xp + 4);
        #pragma unroll
        for (int kk = 0; kk < 32; kk++) {
            float xv = __shfl_sync(0xffffffffu, xf[kk & 7], srcq | (kk >> 3), 32);
            ulonglong2 wv = *(const ulonglong2*)(Wb + (kq*32 + kk)*64);
            unsigned long long xx;
            asm("mov.b64 %0, {%1,%1};" : "=l"(xx) : "f"(xv));
            asm("fma.rn.f32x2 %0, %2, %3, %0;\n\t"
                "fma.rn.f32x2 %1, %2, %4, %1;"
                : "+l"(acc01), "+l"(acc23) : "l"(xx), "l"(wv.x), "l"(wv.y));
        }
    }

    for (int st = 0; st < T; st++) {
        // ---- stage this step's spike bits (1 x LDG.128.cg + STS.128 per thread)
        ((uint4*)sb)[tid] = __ldcg((const uint4*)g_sbits[st & 1] + tid);
        __syncthreads();

        // ---- sparse row-gather (rows kq*512 .. +511) into acc (already holds U)
        #pragma unroll 1
        for (int wi = 0; wi < 16; wi++) {
            unsigned w = wp[wi];
            const int rb = kq*512 + wi*32;
            if (w) {
                int i = __ffs((int)w) - 1; w &= w - 1u;
                int r = rb + i;
                ulonglong2 av = *(const ulonglong2*)(Ab + (r << 6) + ((jg ^ ((r >> 1) & 3)) << 4));
                while (w) {
                    int i2 = __ffs((int)w) - 1; w &= w - 1u;
                    int r2 = rb + i2;
                    ulonglong2 av2 = *(const ulonglong2*)(Ab + (r2 << 6) + ((jg ^ ((r2 >> 1) & 3)) << 4));
                    ACC2(av);
                    av = av2;
                }
                ACC2(av);
            }
        }

        // ---- cross-quarter reduction (fixed order)
        if (kq) {
            ulonglong2 v; v.x = acc01; v.y = acc23;
            *(ulonglong2*)(red + (size_t)(kq-1)*4096 + (tid & 255)*16) = v;
        }
        __syncthreads();

        if (tid < 256) {
            #pragma unroll
            for (int s = 0; s < 3; s++) {
                ulonglong2 v = *(const ulonglong2*)(red + (size_t)s*4096 + tid*16);
                ACC2(v);
            }
            float r0, r1, r2, r3;
            asm("mov.b64 {%0,%1}, %2;" : "=f"(r0), "=f"(r1) : "l"(acc01));
            asm("mov.b64 {%0,%1}, %2;" : "=f"(r2), "=f"(r3) : "l"(acc23));

            float4 y;
            y.x = tanhf(0.5f*r0 + 0.5f*biasv.x);
            y.y = tanhf(0.5f*r1 + 0.5f*biasv.y);
            y.z = tanhf(0.5f*r2 + 0.5f*biasv.z);
            y.w = tanhf(0.5f*r3 + 0.5f*biasv.w);

            mem.x = mem.x*0.5f - 0.5f*(1.0f - spk.x) + y.x;
            mem.y = mem.y*0.5f - 0.5f*(1.0f - spk.y) + y.y;
            mem.z = mem.z*0.5f - 0.5f*(1.0f - spk.z) + y.z;
            mem.w = mem.w*0.5f - 0.5f*(1.0f - spk.w) + y.w;

            spk.x = (mem.x > 0.5f) ? 1.0f : 0.0f;
            spk.y = (mem.y > 0.5f) ? 1.0f : 0.0f;
            spk.z = (mem.z > 0.5f) ? 1.0f : 0.0f;
            spk.w = (mem.w > 0.5f) ? 1.0f : 0.0f;

            const size_t base = (size_t)(b*T + st)*N_HID + j0_e;
            *(float4*)&out[base]            = mem;
            *(float4*)&out[OUT_HALF + base] = spk;

            // ---- pack 16 spike bits via quad shuffles; lane jg==0 publishes
            unsigned v = ((spk.x != 0.f ? 1u : 0u) | (spk.y != 0.f ? 2u : 0u)
                        | (spk.z != 0.f ? 4u : 0u) | (spk.w != 0.f ? 8u : 0u)) << (jg*4);
            v |= __shfl_xor_sync(0xffffffffu, v, 1, 32);
            v |= __shfl_xor_sync(0xffffffffu, v, 2, 32);
            if (jg == 0)
                ((unsigned short*)g_sbits[(st + 1) & 1])[(size_t)b*(N_HID/16) + c] =
                    (unsigned short)v;
        }

        // ---- grid barrier (CG pattern, thread-0-only fences), U(st+1) in slack
        const unsigned target = (unsigned)(st + 1);
        __syncthreads();                       // all publishes + sb reads done
        if (tid == 0) {
            __threadfence();                   // release (cumulative via bar.sync)
            unsigned old = atomicAdd(&g_arrive, 1u);
            if ((old & (NB - 1u)) == (NB - 1u)) {
                __threadfence();
                g_epoch = target;              // volatile release store
            }
        }

        // ---- U-partial for step st+1 (true slack: only tid 0 will spin)
        acc01 = 0ull; acc23 = 0ull;
        if (st + 1 < T) {
            const float* xp = x + ((size_t)b*T + (st + 1))*N_IN + kq*32 + jg*8;
            float xf[8];
            *(float4*)&xf[0] = *(const float4*)xp;
            *(float4*)&xf[4] = *(const float4*)(xp + 4);
            #pragma unroll
            for (int kk = 0; kk < 32; kk++) {
                float xv = __shfl_sync(0xffffffffu, xf[kk & 7], srcq | (kk >> 3), 32);
                ulonglong2 wv = *(const ulonglong2*)(Wb + (kq*32 + kk)*64);
                unsigned long long xx;
                asm("mov.b64 %0, {%1,%1};" : "=l"(xx) : "f"(xv));
                asm("fma.rn.f32x2 %0, %2, %3, %0;\n\t"
                    "fma.rn.f32x2 %1, %2, %4, %1;"
                    : "+l"(acc01), "+l"(acc23) : "l"(xx), "l"(wv.x), "l"(wv.y));
            }
        }

        if (tid == 0) {
            while (g_epoch < target) { }       // volatile spin
            __threadfence();                   // acquire
        }
        __syncthreads();                       // propagate CTA-wide
    }
}

// ---------------- launch ----------------
extern "C" void kernel_launch(void* const* d_in, const int* in_sizes, int n_in,
                              void* d_out, int out_size) {
    const float* x    = (const float*)d_in[0];
    const float* W_in = (const float*)d_in[1];
    const float* A    = (const float*)d_in[2];
    const float* bias = (const float*)d_in[3];
    const float* mem0 = (const float*)d_in[4];
    float* out = (float*)d_out;

    cudaFuncSetAttribute(step_kernel, cudaFuncAttributeMaxDynamicSharedMemorySize,
                         SM_TOTAL);

    init_kernel<<<1, 256>>>();
    step_kernel<<<NB, NTH, SM_TOTAL>>>(x, W_in, A, bias, mem0, out);
}

// round 9
// speedup vs baseline: 6.7898x; 1.1677x over previous
#include <cuda_runtime.h>
#include <cstdint>

#define B      64
#define T      256
#define N_IN   128
#define N_HID  2048
#define NB     128            // persistent CTAs (1 per SM)
#define TILE_J 16             // columns of A per CTA
#define NTH    1024
#define OUT_HALF (B*T*N_HID)
#define SBW    64             // spike-bit words per batch

// SMEM layout (step kernel)
#define SM_AS_BYTES (N_HID*TILE_J*4)                 // 131072 (swizzled, 64B rows)
#define SM_RED_OFF  SM_AS_BYTES
#define SM_RED_BYTES (3*256*16)                      // 12288
#define SM_W_OFF    (SM_RED_OFF + SM_RED_BYTES)
#define SM_W_BYTES  (N_IN*TILE_J*4)                  // 8192
#define SM_U2_OFF   (SM_W_OFF + SM_W_BYTES)
#define SM_U2_BYTES (NTH*16)                         // 16384 (U(st+2) stash)
#define SM_TOTAL    (SM_U2_OFF + SM_U2_BYTES)        // 167936

// ---------------- scratch ----------------
__device__ unsigned int g_sbits[2][B*SBW];           // double-buffered packed spikes
__device__ unsigned int g_arrive;
__device__ volatile unsigned int g_epoch;

// ---------------- init: reset barrier + zero initial spikes ----------------
__global__ void init_kernel() {
    int t = threadIdx.x;
    if (t == 0) { g_arrive = 0u; g_epoch = 0u; }
    for (int i = t; i < B*SBW; i += blockDim.x) g_sbits[0][i] = 0u;
}

#define ACC2(av) asm("add.rn.f32x2 %0, %0, %2;\n\t" \
                     "add.rn.f32x2 %1, %1, %3;"     \
                     : "+l"(acc01), "+l"(acc23) : "l"((av).x), "l"((av).y))

// sparse row-gather over one 32-row spike word (R8-proven inner loop)
#define GW(wword, wi) do {                                                         \
    unsigned w = (wword);                                                          \
    const int rb = kq*512 + (wi)*32;                                               \
    if (w) {                                                                       \
        int i = __ffs((int)w) - 1; w &= w - 1u;                                    \
        int r = rb + i;                                                            \
        ulonglong2 av = *(const ulonglong2*)(Ab + (r << 6) + ((jg ^ ((r >> 1) & 3)) << 4)); \
        while (w) {                                                                \
            int i2 = __ffs((int)w) - 1; w &= w - 1u;                               \
            int r2 = rb + i2;                                                      \
            ulonglong2 av2 = *(const ulonglong2*)(Ab + (r2 << 6) + ((jg ^ ((r2 >> 1) & 3)) << 4)); \
            ACC2(av);                                                              \
            av = av2;                                                              \
        }                                                                          \
        ACC2(av);                                                                  \
    }                                                                              \
} while (0)

// ---------------- persistent step kernel ----------------
// CTA c owns cols [c*16, c*16+16).
// Thread map: jg = tid&3 (col quad), b = (tid>>2)&63 (batch), kq = tid>>8 (quarter).
// Per step: acc = U-partial (prepared last iteration in barrier slack) + sparse
// row-gather over this quarter's spike bits, read DIRECTLY from gmem via
// prefetch-pipelined __ldcg uint4 loads (no smem staging, no extra sync).
// U batching: even steps compute U(st+1) AND U(st+2) in one W-tile pass
// (halving per-step W smem re-reads); U(st+2) parks in a private smem slot.
__global__ void __launch_bounds__(NTH, 1)
step_kernel(const float* __restrict__ x,
            const float* __restrict__ W_in,
            const float* __restrict__ A,
            const float* __restrict__ bias,
            const float* __restrict__ mem0,
            float* __restrict__ out) {
    extern __shared__ unsigned char smem_raw[];
    float*         As  = (float*)smem_raw;                   // swizzled [2048][16]
    unsigned char* red = smem_raw + SM_RED_OFF;
    float*         Ws  = (float*)(smem_raw + SM_W_OFF);      // [128][16]
    unsigned char* u2  = smem_raw + SM_U2_OFF;               // per-thread 16B stash

    const int c    = blockIdx.x;
    const int tid  = threadIdx.x;
    const int lane = tid & 31;
    const int jg   = tid & 3;
    const int b    = (tid >> 2) & 63;
    const int kq   = tid >> 8;

    // A tile, swizzled: word(r,jj) -> r*16 + ((jj>>2 ^ ((r>>1)&3))<<2) + (jj&3)
    for (int idx = tid; idx < N_HID*TILE_J; idx += NTH) {
        int r = idx >> 4, jj = idx & 15;
        int d = (r << 4) + ((((jj >> 2) ^ ((r >> 1) & 3)) << 2)) + (jj & 3);
        As[d] = A[(size_t)r*N_HID + c*TILE_J + jj];
    }
    // W_in tile (plain [k][16])
    for (int idx = tid; idx < N_IN*TILE_J; idx += NTH) {
        int k = idx >> 4, jj = idx & 15;
        Ws[idx] = W_in[(size_t)k*N_HID + c*TILE_J + jj];
    }

    // epilogue persistent state (tid < 256)
    float4 mem = make_float4(0.f,0.f,0.f,0.f);
    float4 spk = make_float4(0.f,0.f,0.f,0.f);
    float4 biasv = make_float4(0.f,0.f,0.f,0.f);
    const int j0_e = c*TILE_J + jg*4;
    if (tid < 256) {
        mem   = *(const float4*)&mem0[(size_t)b*N_HID + j0_e];
        biasv = *(const float4*)&bias[j0_e];
    }
    __syncthreads();

    const unsigned char* Ab   = (const unsigned char*)As;
    const unsigned char* Wb   = (const unsigned char*)Ws + jg*16;
    unsigned char*       u2p  = u2 + tid*16;
    const int            srcq = lane & 28;            // quad base lane for shfl

    // ---- U-partial for step 0 (pre-loop, single step) ----
    unsigned long long acc01 = 0ull, acc23 = 0ull;
    {
        const float* xp = x + ((size_t)b*T + 0)*N_IN + kq*32 + jg*8;
        float xf[8];
        *(float4*)&xf[0] = *(const float4*)xp;
        *(float4*)&xf[4] = *(const float4*)(xp + 4);
        #pragma unroll
        for (int kk = 0; kk < 32; kk++) {
            float xv = __shfl_sync(0xffffffffu, xf[kk & 7], srcq | (kk >> 3), 32);
            ulonglong2 wv = *(const ulonglong2*)(Wb + (kq*32 + kk)*64);
            unsigned long long xx;
            asm("mov.b64 %0, {%1,%1};" : "=l"(xx) : "f"(xv));
            asm("fma.rn.f32x2 %0, %2, %3, %0;\n\t"
                "fma.rn.f32x2 %1, %2, %4, %1;"
                : "+l"(acc01), "+l"(acc23) : "l"(xx), "l"(wv.x), "l"(wv.y));
        }
    }

    for (int st = 0; st < T; st++) {
        // ---- spike words: direct prefetch-pipelined gmem reads (no staging)
        const uint4* gw = (const uint4*)g_sbits[st & 1] + (b*16 + kq*4);
        uint4 wa = __ldcg(gw);
        uint4 wb = __ldcg(gw + 1);

        GW(wa.x, 0); GW(wa.y, 1); GW(wa.z, 2); GW(wa.w, 3);
        wa = __ldcg(gw + 2);
        GW(wb.x, 4); GW(wb.y, 5); GW(wb.z, 6); GW(wb.w, 7);
        wb = __ldcg(gw + 3);
        GW(wa.x, 8);  GW(wa.y, 9);  GW(wa.z, 10); GW(wa.w, 11);
        GW(wb.x, 12); GW(wb.y, 13); GW(wb.z, 14); GW(wb.w, 15);

        // ---- cross-quarter reduction (fixed order)
        if (kq) {
            ulonglong2 v; v.x = acc01; v.y = acc23;
            *(ulonglong2*)(red + (size_t)(kq-1)*4096 + (tid & 255)*16) = v;
        }
        __syncthreads();

        if (tid < 256) {
            #pragma unroll
            for (int s = 0; s < 3; s++) {
                ulonglong2 v = *(const ulonglong2*)(red + (size_t)s*4096 + tid*16);
                ACC2(v);
            }
            float r0, r1, r2, r3;
            asm("mov.b64 {%0,%1}, %2;" : "=f"(r0), "=f"(r1) : "l"(acc01));
            asm("mov.b64 {%0,%1}, %2;" : "=f"(r2), "=f"(r3) : "l"(acc23));

            float4 y;
            y.x = tanhf(0.5f*r0 + 0.5f*biasv.x);
            y.y = tanhf(0.5f*r1 + 0.5f*biasv.y);
            y.z = tanhf(0.5f*r2 + 0.5f*biasv.z);
            y.w = tanhf(0.5f*r3 + 0.5f*biasv.w);

            mem.x = mem.x*0.5f - 0.5f*(1.0f - spk.x) + y.x;
            mem.y = mem.y*0.5f - 0.5f*(1.0f - spk.y) + y.y;
            mem.z = mem.z*0.5f - 0.5f*(1.0f - spk.z) + y.z;
            mem.w = mem.w*0.5f - 0.5f*(1.0f - spk.w) + y.w;

            spk.x = (mem.x > 0.5f) ? 1.0f : 0.0f;
            spk.y = (mem.y > 0.5f) ? 1.0f : 0.0f;
            spk.z = (mem.z > 0.5f) ? 1.0f : 0.0f;
            spk.w = (mem.w > 0.5f) ? 1.0f : 0.0f;

            const size_t base = (size_t)(b*T + st)*N_HID + j0_e;
            *(float4*)&out[base]            = mem;
            *(float4*)&out[OUT_HALF + base] = spk;

            // ---- pack 16 spike bits via quad shuffles; lane jg==0 publishes
            unsigned v = ((spk.x != 0.f ? 1u : 0u) | (spk.y != 0.f ? 2u : 0u)
                        | (spk.z != 0.f ? 4u : 0u) | (spk.w != 0.f ? 8u : 0u)) << (jg*4);
            v |= __shfl_xor_sync(0xffffffffu, v, 1, 32);
            v |= __shfl_xor_sync(0xffffffffu, v, 2, 32);
            if (jg == 0)
                ((unsigned short*)g_sbits[(st + 1) & 1])[(size_t)b*(N_HID/16) + c] =
                    (unsigned short)v;
        }

        // ---- grid barrier arrive (CG pattern, thread-0-only fences)
        const unsigned target = (unsigned)(st + 1);
        __syncthreads();                       // publishes done CTA-wide
        if (tid == 0) {
            __threadfence();                   // release (cumulative via bar.sync)
            unsigned old = atomicAdd(&g_arrive, 1u);
            if ((old & (NB - 1u)) == (NB - 1u)) {
                __threadfence();
                g_epoch = target;              // volatile release store
            }
        }

        // ---- barrier slack: prepare U for next step(s)
        acc01 = 0ull; acc23 = 0ull;
        if (st + 1 < T) {
            if ((st & 1) == 0) {
                // compute U(st+1) into acc, and U(st+2) into stash (one W pass)
                const bool do2 = (st + 2 < T);
                const float* xp1 = x + ((size_t)b*T + (st + 1))*N_IN + kq*32 + jg*8;
                const float* xp2 = x + ((size_t)b*T + (do2 ? st + 2 : st + 1))*N_IN + kq*32 + jg*8;
                float xf1[8], xf2[8];
                *(float4*)&xf1[0] = *(const float4*)xp1;
                *(float4*)&xf1[4] = *(const float4*)(xp1 + 4);
                *(float4*)&xf2[0] = *(const float4*)xp2;
                *(float4*)&xf2[4] = *(const float4*)(xp2 + 4);
                unsigned long long d01 = 0ull, d23 = 0ull;
                #pragma unroll
                for (int kk = 0; kk < 32; kk++) {
                    float xv1 = __shfl_sync(0xffffffffu, xf1[kk & 7], srcq | (kk >> 3), 32);
                    float xv2 = __shfl_sync(0xffffffffu, xf2[kk & 7], srcq | (kk >> 3), 32);
                    ulonglong2 wv = *(const ulonglong2*)(Wb + (kq*32 + kk)*64);
                    unsigned long long xx1, xx2;
                    asm("mov.b64 %0, {%1,%1};" : "=l"(xx1) : "f"(xv1));
                    asm("mov.b64 %0, {%1,%1};" : "=l"(xx2) : "f"(xv2));
                    asm("fma.rn.f32x2 %0, %2, %3, %0;\n\t"
                        "fma.rn.f32x2 %1, %2, %4, %1;"
                        : "+l"(acc01), "+l"(acc23) : "l"(xx1), "l"(wv.x), "l"(wv.y));
                    asm("fma.rn.f32x2 %0, %2, %3, %0;\n\t"
                        "fma.rn.f32x2 %1, %2, %4, %1;"
                        : "+l"(d01), "+l"(d23) : "l"(xx2), "l"(wv.x), "l"(wv.y));
                }
                if (do2) {
                    ulonglong2 v; v.x = d01; v.y = d23;
                    *(ulonglong2*)u2p = v;
                }
            } else {
                // odd step: U(st+1) was stashed last iteration (same thread)
                ulonglong2 v = *(const ulonglong2*)u2p;
                acc01 = v.x; acc23 = v.y;
            }
        }

        if (tid == 0) {
            while (g_epoch < target) { }       // volatile spin
            __threadfence();                   // acquire
        }
        __syncthreads();                       // propagate CTA-wide
    }
}

// ---------------- launch ----------------
extern "C" void kernel_launch(void* const* d_in, const int* in_sizes, int n_in,
                              void* d_out, int out_size) {
    const float* x    = (const float*)d_in[0];
    const float* W_in = (const float*)d_in[1];
    const float* A    = (const float*)d_in[2];
    const float* bias = (const float*)d_in[3];
    const float* mem0 = (const float*)d_in[4];
    float* out = (float*)d_out;

    cudaFuncSetAttribute(step_kernel, cudaFuncAttributeMaxDynamicSharedMemorySize,
                         SM_TOTAL);

    init_kernel<<<1, 256>>>();
    step_kernel<<<NB, NTH, SM_TOTAL>>>(x, W_in, A, bias, mem0, out);
}

// round 13
// speedup vs baseline: 7.4620x; 1.0990x over previous
#include <cuda_runtime.h>
#include <cstdint>

#define B      64
#define T      256
#define N_IN   128
#define N_HID  2048
#define NB     128            // persistent CTAs (1 per SM)
#define TILE_J 16             // columns of A per CTA
#define NTH    1024
#define OUT_HALF (B*T*N_HID)
#define SBW    64             // spike-bit words per batch

// SMEM layout (step kernel) — no reduction scratch needed anymore
#define SM_AS_BYTES (N_HID*TILE_J*4)                 // 131072 (swizzled, 64B rows)
#define SM_W_OFF    SM_AS_BYTES
#define SM_W_BYTES  (N_IN*TILE_J*4)                  // 8192
#define SM_U2_OFF   (SM_W_OFF + SM_W_BYTES)
#define SM_U2_BYTES (NTH*16)                         // 16384 (U(st+2) stash)
#define SM_TOTAL    (SM_U2_OFF + SM_U2_BYTES)        // 155648

// ---------------- scratch ----------------
__device__ unsigned int g_sbits[2][B*SBW];           // double-buffered packed spikes
__device__ unsigned int g_arrive;
__device__ volatile unsigned int g_epoch;

// ---------------- init: reset barrier + zero initial spikes ----------------
__global__ void init_kernel() {
    int t = threadIdx.x;
    if (t == 0) { g_arrive = 0u; g_epoch = 0u; }
    for (int i = t; i < B*SBW; i += blockDim.x) g_sbits[0][i] = 0u;
}

#define ACC2(av) asm("add.rn.f32x2 %0, %0, %2;\n\t" \
                     "add.rn.f32x2 %1, %1, %3;"     \
                     : "+l"(acc01), "+l"(acc23) : "l"((av).x), "l"((av).y))

// sparse row-gather over one 32-row spike word (proven inner loop)
#define GW(wword, rbase) do {                                                      \
    unsigned w = (wword);                                                          \
    const int rb = (rbase);                                                        \
    if (w) {                                                                       \
        int i = __ffs((int)w) - 1; w &= w - 1u;                                    \
        int r = rb + i;                                                            \
        ulonglong2 av = *(const ulonglong2*)(Ab + (r << 6) + ((jg ^ ((r >> 1) & 3)) << 4)); \
        while (w) {                                                                \
            int i2 = __ffs((int)w) - 1; w &= w - 1u;                               \
            int r2 = rb + i2;                                                      \
            ulonglong2 av2 = *(const ulonglong2*)(Ab + (r2 << 6) + ((jg ^ ((r2 >> 1) & 3)) << 4)); \
            ACC2(av);                                                              \
            av = av2;                                                              \
        }                                                                          \
        ACC2(av);                                                                  \
    }                                                                              \
} while (0)

// ---------------- persistent step kernel (R9 sync, in-warp quarter reduction) ---
// CTA c owns cols [c*16, c*16+16).
// NEW thread map: warp wid owns 8 units; unit = wid*8 + (lane&7) = b*4 + jg,
// kq = lane>>3. The 4 K-quarters of a unit sit in ONE warp at lanes {u, u+8,
// u+16, u+24}: cross-quarter reduction = 3 shfl_down (8,16,24) + sequential
// adds in R9's exact order (bit-identical) — no smem scratch, no extra sync.
// Lanes 0-7 (kq==0) own the epilogue for their unit. Everything else (gather,
// direct __ldcg spike reads, U batching in barrier slack, volatile-spin grid
// barrier) is byte-for-byte the proven R9 structure.
__global__ void __launch_bounds__(NTH, 1)
step_kernel(const float* __restrict__ x,
            const float* __restrict__ W_in,
            const float* __restrict__ A,
            const float* __restrict__ bias,
            const float* __restrict__ mem0,
            float* __restrict__ out) {
    extern __shared__ unsigned char smem_raw[];
    float*         As  = (float*)smem_raw;                   // swizzled [2048][16]
    float*         Ws  = (float*)(smem_raw + SM_W_OFF);      // [128][16]
    unsigned char* u2  = smem_raw + SM_U2_OFF;               // per-thread 16B stash

    const int c    = blockIdx.x;
    const int tid  = threadIdx.x;
    const int lane = tid & 31;
    const int wid  = tid >> 5;
    const int unit = wid*8 + (lane & 7);       // 0..255 = b*4 + jg
    const int jg   = unit & 3;
    const int b    = unit >> 2;
    const int kq   = lane >> 3;                // 0..3

    // A tile, swizzled: word(r,jj) -> r*16 + ((jj>>2 ^ ((r>>1)&3))<<2) + (jj&3)
    for (int idx = tid; idx < N_HID*TILE_J; idx += NTH) {
        int r = idx >> 4, jj = idx & 15;
        int d = (r << 4) + ((((jj >> 2) ^ ((r >> 1) & 3)) << 2)) + (jj & 3);
        As[d] = A[(size_t)r*N_HID + c*TILE_J + jj];
    }
    // W_in tile (plain [k][16])
    for (int idx = tid; idx < N_IN*TILE_J; idx += NTH) {
        int k = idx >> 4, jj = idx & 15;
        Ws[idx] = W_in[(size_t)k*N_HID + c*TILE_J + jj];
    }

    // epilogue persistent state (owner lanes: kq == 0, i.e. lane < 8)
    float4 mem = make_float4(0.f,0.f,0.f,0.f);
    float4 spk = make_float4(0.f,0.f,0.f,0.f);
    float4 biasv = make_float4(0.f,0.f,0.f,0.f);
    const int j0_e = c*TILE_J + jg*4;
    if (kq == 0) {
        mem   = *(const float4*)&mem0[(size_t)b*N_HID + j0_e];
        biasv = *(const float4*)&bias[j0_e];
    }
    __syncthreads();

    const unsigned char* Ab   = (const unsigned char*)As;
    const unsigned char* Wb   = (const unsigned char*)Ws + jg*16;
    unsigned char*       u2p  = u2 + tid*16;
    const int            srcq = lane & 28;     // quad base (same b,kq; jg 0-3)

    // ---- U-partial for step 0 (pre-loop, single step) ----
    unsigned long long acc01 = 0ull, acc23 = 0ull;
    {
        const float* xp = x + ((size_t)b*T + 0)*N_IN + kq*32 + jg*8;
        float xf[8];
        *(float4*)&xf[0] = *(const float4*)xp;
        *(float4*)&xf[4] = *(const float4*)(xp + 4);
        #pragma unroll
        for (int kk = 0; kk < 32; kk++) {
            float xv = __shfl_sync(0xffffffffu, xf[kk & 7], srcq | (kk >> 3), 32);
            ulonglong2 wv = *(const ulonglong2*)(Wb + (kq*32 + kk)*64);
            unsigned long long xx;
            asm("mov.b64 %0, {%1,%1};" : "=l"(xx) : "f"(xv));
            asm("fma.rn.f32x2 %0, %2, %3, %0;\n\t"
                "fma.rn.f32x2 %1, %2, %4, %1;"
                : "+l"(acc01), "+l"(acc23) : "l"(xx), "l"(wv.x), "l"(wv.y));
        }
    }

    for (int st = 0; st < T; st++) {
        // ---- spike words: direct prefetch-pipelined gmem reads (R9-proven)
        const uint4* gw = (const uint4*)g_sbits[st & 1] + (b*16 + kq*4);
        uint4 wa = __ldcg(gw);
        uint4 wb = __ldcg(gw + 1);

        GW(wa.x, kq*512 + 0*32);  GW(wa.y, kq*512 + 1*32);
        GW(wa.z, kq*512 + 2*32);  GW(wa.w, kq*512 + 3*32);
        wa = __ldcg(gw + 2);
        GW(wb.x, kq*512 + 4*32);  GW(wb.y, kq*512 + 5*32);
        GW(wb.z, kq*512 + 6*32);  GW(wb.w, kq*512 + 7*32);
        wb = __ldcg(gw + 3);
        GW(wa.x, kq*512 + 8*32);  GW(wa.y, kq*512 + 9*32);
        GW(wa.z, kq*512 + 10*32); GW(wa.w, kq*512 + 11*32);
        GW(wb.x, kq*512 + 12*32); GW(wb.y, kq*512 + 13*32);
        GW(wb.z, kq*512 + 14*32); GW(wb.w, kq*512 + 15*32);

        // ---- cross-quarter reduction: in-warp shfl, R9's exact add order
        unsigned long long p01a = __shfl_down_sync(0xffffffffu, acc01, 8, 32);
        unsigned long long p23a = __shfl_down_sync(0xffffffffu, acc23, 8, 32);
        unsigned long long p01b = __shfl_down_sync(0xffffffffu, acc01, 16, 32);
        unsigned long long p23b = __shfl_down_sync(0xffffffffu, acc23, 16, 32);
        unsigned long long p01c = __shfl_down_sync(0xffffffffu, acc01, 24, 32);
        unsigned long long p23c = __shfl_down_sync(0xffffffffu, acc23, 24, 32);

        if (kq == 0) {
            asm("add.rn.f32x2 %0, %0, %1;" : "+l"(acc01) : "l"(p01a));
            asm("add.rn.f32x2 %0, %0, %1;" : "+l"(acc23) : "l"(p23a));
            asm("add.rn.f32x2 %0, %0, %1;" : "+l"(acc01) : "l"(p01b));
            asm("add.rn.f32x2 %0, %0, %1;" : "+l"(acc23) : "l"(p23b));
            asm("add.rn.f32x2 %0, %0, %1;" : "+l"(acc01) : "l"(p01c));
            asm("add.rn.f32x2 %0, %0, %1;" : "+l"(acc23) : "l"(p23c));

            float r0, r1, r2, r3;
            asm("mov.b64 {%0,%1}, %2;" : "=f"(r0), "=f"(r1) : "l"(acc01));
            asm("mov.b64 {%0,%1}, %2;" : "=f"(r2), "=f"(r3) : "l"(acc23));

            float4 y;
            y.x = tanhf(0.5f*r0 + 0.5f*biasv.x);
            y.y = tanhf(0.5f*r1 + 0.5f*biasv.y);
            y.z = tanhf(0.5f*r2 + 0.5f*biasv.z);
            y.w = tanhf(0.5f*r3 + 0.5f*biasv.w);

            mem.x = mem.x*0.5f - 0.5f*(1.0f - spk.x) + y.x;
            mem.y = mem.y*0.5f - 0.5f*(1.0f - spk.y) + y.y;
            mem.z = mem.z*0.5f - 0.5f*(1.0f - spk.z) + y.z;
            mem.w = mem.w*0.5f - 0.5f*(1.0f - spk.w) + y.w;

            spk.x = (mem.x > 0.5f) ? 1.0f : 0.0f;
            spk.y = (mem.y > 0.5f) ? 1.0f : 0.0f;
            spk.z = (mem.z > 0.5f) ? 1.0f : 0.0f;
            spk.w = (mem.w > 0.5f) ? 1.0f : 0.0f;

            const size_t base = (size_t)(b*T + st)*N_HID + j0_e;
            *(float4*)&out[base]            = mem;
            *(float4*)&out[OUT_HALF + base] = spk;

            // ---- pack 16 spike bits within lanes 0-7 (two b's per warp)
            unsigned v = ((spk.x != 0.f ? 1u : 0u) | (spk.y != 0.f ? 2u : 0u)
                        | (spk.z != 0.f ? 4u : 0u) | (spk.w != 0.f ? 8u : 0u)) << (jg*4);
            v |= __shfl_xor_sync(0xFFu, v, 1, 32);
            v |= __shfl_xor_sync(0xFFu, v, 2, 32);
            if (jg == 0)
                ((unsigned short*)g_sbits[(st + 1) & 1])[(size_t)b*(N_HID/16) + c] =
                    (unsigned short)v;
        }

        // ---- grid barrier (R9-proven: CG pattern, thread-0-only fences)
        const unsigned target = (unsigned)(st + 1);
        __syncthreads();                       // publishes done CTA-wide
        if (tid == 0) {
            __threadfence();                   // release (cumulative via bar.sync)
            unsigned old = atomicAdd(&g_arrive, 1u);
            if ((old & (NB - 1u)) == (NB - 1u)) {
                __threadfence();
                g_epoch = target;              // volatile release store
            }
        }

        // ---- barrier slack: prepare U for next step(s) (R9-proven batching)
        acc01 = 0ull; acc23 = 0ull;
        if (st + 1 < T) {
            if ((st & 1) == 0) {
                const bool do2 = (st + 2 < T);
                const float* xp1 = x + ((size_t)b*T + (st + 1))*N_IN + kq*32 + jg*8;
                const float* xp2 = x + ((size_t)b*T + (do2 ? st + 2 : st + 1))*N_IN + kq*32 + jg*8;
                float xf1[8], xf2[8];
                *(float4*)&xf1[0] = *(const float4*)xp1;
                *(float4*)&xf1[4] = *(const float4*)(xp1 + 4);
                *(float4*)&xf2[0] = *(const float4*)xp2;
                *(float4*)&xf2[4] = *(const float4*)(xp2 + 4);
                unsigned long long d01 = 0ull, d23 = 0ull;
                #pragma unroll
                for (int kk = 0; kk < 32; kk++) {
                    float xv1 = __shfl_sync(0xffffffffu, xf1[kk & 7], srcq | (kk >> 3), 32);
                    float xv2 = __shfl_sync(0xffffffffu, xf2[kk & 7], srcq | (kk >> 3), 32);
                    ulonglong2 wv = *(const ulonglong2*)(Wb + (kq*32 + kk)*64);
                    unsigned long long xx1, xx2;
                    asm("mov.b64 %0, {%1,%1};" : "=l"(xx1) : "f"(xv1));
                    asm("mov.b64 %0, {%1,%1};" : "=l"(xx2) : "f"(xv2));
                    asm("fma.rn.f32x2 %0, %2, %3, %0;\n\t"
                        "fma.rn.f32x2 %1, %2, %4, %1;"
                        : "+l"(acc01), "+l"(acc23) : "l"(xx1), "l"(wv.x), "l"(wv.y));
                    asm("fma.rn.f32x2 %0, %2, %3, %0;\n\t"
                        "fma.rn.f32x2 %1, %2, %4, %1;"
                        : "+l"(d01), "+l"(d23) : "l"(xx2), "l"(wv.x), "l"(wv.y));
                }
                if (do2) {
                    ulonglong2 v; v.x = d01; v.y = d23;
                    *(ulonglong2*)u2p = v;
                }
            } else {
                ulonglong2 v = *(const ulonglong2*)u2p;
                acc01 = v.x; acc23 = v.y;
            }
        }

        if (tid == 0) {
            while (g_epoch < target) { }       // volatile spin
            __threadfence();                   // acquire
        }
        __syncthreads();                       // propagate CTA-wide
    }
}

// ---------------- launch ----------------
extern "C" void kernel_launch(void* const* d_in, const int* in_sizes, int n_in,
                              void* d_out, int out_size) {
    const float* x    = (const float*)d_in[0];
    const float* W_in = (const float*)d_in[1];
    const float* A    = (const float*)d_in[2];
    const float* bias = (const float*)d_in[3];
    const float* mem0 = (const float*)d_in[4];
    float* out = (float*)d_out;

    cudaFuncSetAttribute(step_kernel, cudaFuncAttributeMaxDynamicSharedMemorySize,
                         SM_TOTAL);

    init_kernel<<<1, 256>>>();
    step_kernel<<<NB, NTH, SM_TOTAL>>>(x, W_in, A, bias, mem0, out);
}